// round 2
// baseline (speedup 1.0000x reference)
#include <cuda_runtime.h>
#include <cuda_bf16.h>

#define NN 100000
#define NE 1600000
#define FEATS 128
#define HID 64
#define NCLS 40
#define NEG 0.01f

// ---------------- scratch (device globals; no allocations allowed) ----------
__device__ float g_deg[NN];
__device__ float g_dis[NN];
__device__ float g_norm[NE];
__device__ float g_h[(size_t)NN * HID];
__device__ float g_t[(size_t)NN * HID];
__device__ float g_acc[(size_t)NN * HID];
__device__ int   g_is64;

// ---------------- edge index dtype detection --------------------------------
__global__ void detect_i64_kernel(const void* ei) {
    const int* w = (const int*)ei;
    int zeros = 0;
    for (int i = 1; i < 64; i += 2) zeros += (w[i] == 0);
    g_is64 = (zeros == 32) ? 1 : 0;
}

__device__ __forceinline__ long long edge_node(const void* ei, long long idx) {
    if (g_is64) return ((const long long*)ei)[idx];
    return (long long)((const int*)ei)[idx];
}

// ---------------- gcn_norm ---------------------------------------------------
__global__ void deg_init_kernel() {
    int i = blockIdx.x * blockDim.x + threadIdx.x;
    if (i < NN) g_deg[i] = 1.0f;  // self-loop weight
}

__global__ void deg_accum_kernel(const void* __restrict__ ei,
                                 const float* __restrict__ ew) {
    int e = blockIdx.x * blockDim.x + threadIdx.x;
    if (e < NE) {
        long long d = edge_node(ei, (long long)NE + e);
        atomicAdd(&g_deg[d], ew[e]);
    }
}

__global__ void dis_kernel() {
    int i = blockIdx.x * blockDim.x + threadIdx.x;
    if (i < NN) {
        float d = g_deg[i];
        g_dis[i] = (d > 0.f) ? rsqrtf(d) : 0.f;
    }
}

__global__ void norm_kernel(const void* __restrict__ ei,
                            const float* __restrict__ ew) {
    int e = blockIdx.x * blockDim.x + threadIdx.x;
    if (e < NE) {
        long long s = edge_node(ei, e);
        long long d = edge_node(ei, (long long)NE + e);
        g_norm[e] = g_dis[s] * ew[e] * g_dis[d];
    }
}

// ---------------- GEMM: [NN,128] @ [128,64] + b, leaky -> g_h ---------------
__global__ void __launch_bounds__(256)
gemm128_bias_lrelu(const float* __restrict__ A, const float* __restrict__ W,
                   const float* __restrict__ b) {
    __shared__ float Ws[FEATS * HID];   // 32 KB
    __shared__ float Xs[16 * FEATS];    // 8 KB
    int tid = threadIdx.x;
    for (int i = tid; i < FEATS * HID; i += 256) Ws[i] = W[i];
    long long row0 = (long long)blockIdx.x * 16;
    for (int i = tid; i < 16 * FEATS; i += 256) Xs[i] = A[row0 * FEATS + i];
    __syncthreads();

    int col = tid & 63, rg = tid >> 6;   // 4 row-groups x 64 cols
    float acc[4] = {0.f, 0.f, 0.f, 0.f};
#pragma unroll 4
    for (int k = 0; k < FEATS; k++) {
        float w = Ws[k * HID + col];
#pragma unroll
        for (int j = 0; j < 4; j++) acc[j] += Xs[(rg + 4 * j) * FEATS + k] * w;
    }
    float bb = b[col];
#pragma unroll
    for (int j = 0; j < 4; j++) {
        float v = acc[j] + bb;
        g_h[(row0 + rg + 4 * j) * HID + col] = (v > 0.f) ? v : NEG * v;
    }
}

// ---------------- GEMM: g_h[NN,64] @ W[64,64] -> g_t (no bias/act) ----------
__global__ void __launch_bounds__(256)
gemm64(const float* __restrict__ W) {
    __shared__ float Ws[HID * HID];   // 16 KB
    __shared__ float Xs[32 * HID];    // 8 KB
    int tid = threadIdx.x;
    for (int i = tid; i < HID * HID; i += 256) Ws[i] = W[i];
    long long row0 = (long long)blockIdx.x * 32;
    for (int i = tid; i < 32 * HID; i += 256) Xs[i] = g_h[row0 * HID + i];
    __syncthreads();

    int col = tid & 63, rg = tid >> 6;
    float acc[8] = {0.f, 0.f, 0.f, 0.f, 0.f, 0.f, 0.f, 0.f};
#pragma unroll 4
    for (int k = 0; k < HID; k++) {
        float w = Ws[k * HID + col];
#pragma unroll
        for (int j = 0; j < 8; j++) acc[j] += Xs[(rg + 4 * j) * HID + k] * w;
    }
#pragma unroll
    for (int j = 0; j < 8; j++)
        g_t[(row0 + rg + 4 * j) * HID + col] = acc[j];
}

// ---------------- aggregation -----------------------------------------------
// init with self-loop contribution: acc[i,:] = dis[i]^2 * t[i,:]
__global__ void self_init_kernel() {
    long long i = (long long)blockIdx.x * blockDim.x + threadIdx.x;
    if (i < (long long)NN * HID) {
        int node = (int)(i >> 6);
        float d = g_dis[node];
        g_acc[i] = d * d * g_t[i];
    }
}

// one warp per edge: acc[dst,:] += norm[e] * t[src,:]  (vector red, 2 f32/lane)
__global__ void __launch_bounds__(256)
scatter_kernel(const void* __restrict__ ei) {
    long long e = ((long long)blockIdx.x * blockDim.x + threadIdx.x) >> 5;
    int lane = threadIdx.x & 31;
    if (e >= NE) return;
    long long s = edge_node(ei, e);
    long long d = edge_node(ei, (long long)NE + e);
    float nrm = g_norm[e];
    float2 v = ((const float2*)(g_t + s * HID))[lane];
    float a0 = nrm * v.x, a1 = nrm * v.y;
    float* p = &g_acc[d * HID + 2 * lane];
    asm volatile("red.global.add.v2.f32 [%0], {%1, %2};"
                 :: "l"(p), "f"(a0), "f"(a1) : "memory");
}

__global__ void bias_lrelu_kernel(const float* __restrict__ b) {
    long long i = (long long)blockIdx.x * blockDim.x + threadIdx.x;
    if (i < (long long)NN * HID) {
        float v = g_acc[i] + b[i & 63];
        g_h[i] = (v > 0.f) ? v : NEG * v;
    }
}

// ---------------- output: g_h[NN,64]@[64,40] + b, log_softmax ---------------
__global__ void __launch_bounds__(256)
out_kernel(const float* __restrict__ W, const float* __restrict__ b,
           float* __restrict__ out) {
    __shared__ float Ws[HID * NCLS];  // 10 KB
    __shared__ float bs[NCLS];
    int tid = threadIdx.x;
    for (int i = tid; i < HID * NCLS; i += 256) Ws[i] = W[i];
    if (tid < NCLS) bs[tid] = b[tid];
    __syncthreads();

    int warp = tid >> 5, lane = tid & 31;
    long long node = (long long)blockIdx.x * 8 + warp;
    if (node >= NN) return;

    float hv0 = g_h[node * HID + lane];
    float hv1 = g_h[node * HID + 32 + lane];

    float a0 = bs[lane];                         // class = lane
    float a1 = (lane < 8) ? bs[32 + lane] : 0.f; // class = 32+lane
#pragma unroll 8
    for (int k = 0; k < HID; k++) {
        float hk = __shfl_sync(0xffffffffu, (k < 32) ? hv0 : hv1, k & 31);
        a0 += hk * Ws[k * NCLS + lane];
        if (lane < 8) a1 += hk * Ws[k * NCLS + 32 + lane];
    }

    // warp-wide max over 40 valid values
    float m = (lane < 8) ? fmaxf(a0, a1) : a0;
#pragma unroll
    for (int o = 16; o > 0; o >>= 1)
        m = fmaxf(m, __shfl_xor_sync(0xffffffffu, m, o));

    float s = expf(a0 - m) + ((lane < 8) ? expf(a1 - m) : 0.f);
#pragma unroll
    for (int o = 16; o > 0; o >>= 1)
        s += __shfl_xor_sync(0xffffffffu, s, o);

    float lse = m + logf(s);
    out[node * NCLS + lane] = a0 - lse;
    if (lane < 8) out[node * NCLS + 32 + lane] = a1 - lse;
}

// ---------------- launch (kernel launches ONLY — nothing else) ---------------
extern "C" void kernel_launch(void* const* d_in, const int* in_sizes, int n_in,
                              void* d_out, int out_size) {
    const float* x       = (const float*)d_in[0];
    const void*  ei      = d_in[1];               // int32 or int64, detected
    const float* ew      = (const float*)d_in[2];
    const float* W_first = (const float*)d_in[3];
    const float* b_first = (const float*)d_in[4];
    const float* Wc1     = (const float*)d_in[5];
    const float* bc1     = (const float*)d_in[6];
    const float* Wc2     = (const float*)d_in[7];
    const float* bc2     = (const float*)d_in[8];
    const float* W_out   = (const float*)d_in[9];
    const float* b_out   = (const float*)d_in[10];
    float* out = (float*)d_out;

    const int T = 256;
    detect_i64_kernel<<<1, 1>>>(ei);

    // gcn_norm
    deg_init_kernel<<<(NN + T - 1) / T, T>>>();
    deg_accum_kernel<<<(NE + T - 1) / T, T>>>(ei, ew);
    dis_kernel<<<(NN + T - 1) / T, T>>>();
    norm_kernel<<<(NE + T - 1) / T, T>>>(ei, ew);

    // first linear + leaky_relu -> g_h
    gemm128_bias_lrelu<<<NN / 16, T>>>(x, W_first, b_first);

    // conv layer 1
    gemm64<<<NN / 32, T>>>(Wc1);
    self_init_kernel<<<((long long)NN * HID + T - 1) / T, T>>>();
    scatter_kernel<<<NE / 8, T>>>(ei);             // 1 warp per edge
    bias_lrelu_kernel<<<((long long)NN * HID + T - 1) / T, T>>>(bc1);

    // conv layer 2
    gemm64<<<NN / 32, T>>>(Wc2);
    self_init_kernel<<<((long long)NN * HID + T - 1) / T, T>>>();
    scatter_kernel<<<NE / 8, T>>>(ei);
    bias_lrelu_kernel<<<((long long)NN * HID + T - 1) / T, T>>>(bc2);

    // output head + log_softmax
    out_kernel<<<(NN + 7) / 8, T>>>(W_out, b_out, out);
}

// round 3
// speedup vs baseline: 1.7750x; 1.7750x over previous
#include <cuda_runtime.h>
#include <cuda_bf16.h>

#define NN 100000
#define NE 1600000
#define FEATS 128
#define HID 64
#define NCLS 40
#define NEG 0.01f
#define NPART ((NN + 1023) / 1024)

// ---------------- scratch (device globals) -----------------------------------
__device__ float g_deg[NN];
__device__ float g_dis[NN];
__device__ float g_h[(size_t)NN * HID];
__device__ float g_t[(size_t)NN * HID];
__device__ int   g_cnt[NN];
__device__ int   g_fill[NN];
__device__ int   g_rowptr[NN + 1];
__device__ int   g_part[NPART];
__device__ int   g_csr_src[NE];
__device__ float g_csr_norm[NE];
__device__ int   g_is64;

// ---------------- edge index dtype detection ---------------------------------
__global__ void detect_i64_kernel(const void* ei) {
    const int* w = (const int*)ei;
    int zeros = 0;
    for (int i = 1; i < 64; i += 2) zeros += (w[i] == 0);
    g_is64 = (zeros == 32) ? 1 : 0;
}

__device__ __forceinline__ long long edge_node(const void* ei, long long idx) {
    if (g_is64) return ((const long long*)ei)[idx];
    return (long long)((const int*)ei)[idx];
}

// ---------------- gcn_norm + histogram ---------------------------------------
__global__ void init_kernel() {
    int i = blockIdx.x * blockDim.x + threadIdx.x;
    if (i < NN) { g_deg[i] = 1.0f; g_cnt[i] = 0; g_fill[i] = 0; }
}

__global__ void deg_accum_kernel(const void* __restrict__ ei,
                                 const float* __restrict__ ew) {
    int e = blockIdx.x * blockDim.x + threadIdx.x;
    if (e < NE) {
        int d = (int)edge_node(ei, (long long)NE + e);
        atomicAdd(&g_deg[d], ew[e]);
        atomicAdd(&g_cnt[d], 1);
    }
}

__global__ void dis_kernel() {
    int i = blockIdx.x * blockDim.x + threadIdx.x;
    if (i < NN) {
        float d = g_deg[i];
        g_dis[i] = (d > 0.f) ? rsqrtf(d) : 0.f;
    }
}

// ---------------- prefix scan over g_cnt -> g_rowptr -------------------------
__global__ void scan1_kernel() {
    __shared__ int sh[256];
    int t = threadIdx.x;
    int base = blockIdx.x * 1024 + t * 4;
    int s = 0;
#pragma unroll
    for (int j = 0; j < 4; j++) if (base + j < NN) s += g_cnt[base + j];
    sh[t] = s; __syncthreads();
#pragma unroll
    for (int o = 128; o > 0; o >>= 1) {
        if (t < o) sh[t] += sh[t + o];
        __syncthreads();
    }
    if (t == 0) g_part[blockIdx.x] = sh[0];
}

__global__ void scan2_kernel() {
    int run = 0;
    for (int i = 0; i < NPART; i++) { int v = g_part[i]; g_part[i] = run; run += v; }
}

__global__ void scan3_kernel() {
    __shared__ int sh[256];
    int t = threadIdx.x;
    int base = blockIdx.x * 1024 + t * 4;
    int v[4]; int s = 0;
#pragma unroll
    for (int j = 0; j < 4; j++) { v[j] = (base + j < NN) ? g_cnt[base + j] : 0; s += v[j]; }
    sh[t] = s; __syncthreads();
    for (int o = 1; o < 256; o <<= 1) {          // inclusive Hillis-Steele
        int x = (t >= o) ? sh[t - o] : 0;
        __syncthreads();
        sh[t] += x;
        __syncthreads();
    }
    int off = (t == 0) ? 0 : sh[t - 1];
    int b = g_part[blockIdx.x] + off;
    int run = 0;
#pragma unroll
    for (int j = 0; j < 4; j++) {
        if (base + j < NN) g_rowptr[base + j] = b + run;
        run += v[j];
    }
    if (blockIdx.x == 0 && t == 0) g_rowptr[NN] = NE;
}

// ---------------- CSR fill (computes norm inline) ----------------------------
__global__ void fill_kernel(const void* __restrict__ ei,
                            const float* __restrict__ ew) {
    int e = blockIdx.x * blockDim.x + threadIdx.x;
    if (e < NE) {
        int s = (int)edge_node(ei, e);
        int d = (int)edge_node(ei, (long long)NE + e);
        float nrm = g_dis[s] * ew[e] * g_dis[d];
        int pos = g_rowptr[d] + atomicAdd(&g_fill[d], 1);
        g_csr_src[pos] = s;
        g_csr_norm[pos] = nrm;
    }
}

// ---------------- GEMM: [NN,128] @ [128,64] + b, leaky -> g_h ---------------
__global__ void __launch_bounds__(256)
gemm128_bias_lrelu(const float* __restrict__ A, const float* __restrict__ W,
                   const float* __restrict__ b) {
    __shared__ float Ws[FEATS * HID];
    __shared__ float Xs[16 * FEATS];
    int tid = threadIdx.x;
    for (int i = tid; i < FEATS * HID; i += 256) Ws[i] = W[i];
    long long row0 = (long long)blockIdx.x * 16;
    for (int i = tid; i < 16 * FEATS; i += 256) Xs[i] = A[row0 * FEATS + i];
    __syncthreads();

    int col = tid & 63, rg = tid >> 6;
    float acc[4] = {0.f, 0.f, 0.f, 0.f};
#pragma unroll 4
    for (int k = 0; k < FEATS; k++) {
        float w = Ws[k * HID + col];
#pragma unroll
        for (int j = 0; j < 4; j++) acc[j] += Xs[(rg + 4 * j) * FEATS + k] * w;
    }
    float bb = b[col];
#pragma unroll
    for (int j = 0; j < 4; j++) {
        float v = acc[j] + bb;
        g_h[(row0 + rg + 4 * j) * HID + col] = (v > 0.f) ? v : NEG * v;
    }
}

// ---------------- GEMM: g_h[NN,64] @ W[64,64] -> g_t -------------------------
__global__ void __launch_bounds__(256)
gemm64(const float* __restrict__ W) {
    __shared__ float Ws[HID * HID];
    __shared__ float Xs[32 * HID];
    int tid = threadIdx.x;
    for (int i = tid; i < HID * HID; i += 256) Ws[i] = W[i];
    long long row0 = (long long)blockIdx.x * 32;
    for (int i = tid; i < 32 * HID; i += 256) Xs[i] = g_h[row0 * HID + i];
    __syncthreads();

    int col = tid & 63, rg = tid >> 6;
    float acc[8] = {0.f, 0.f, 0.f, 0.f, 0.f, 0.f, 0.f, 0.f};
#pragma unroll 4
    for (int k = 0; k < HID; k++) {
        float w = Ws[k * HID + col];
#pragma unroll
        for (int j = 0; j < 8; j++) acc[j] += Xs[(rg + 4 * j) * HID + k] * w;
    }
#pragma unroll
    for (int j = 0; j < 8; j++)
        g_t[(row0 + rg + 4 * j) * HID + col] = acc[j];
}

// ---------------- aggregation: warp per dst, fused self+bias+leaky ----------
__global__ void __launch_bounds__(256)
agg_kernel(const float* __restrict__ b) {
    int warp = (blockIdx.x * 256 + threadIdx.x) >> 5;
    int lane = threadIdx.x & 31;
    if (warp >= NN) return;
    int d = warp;

    float dd = g_dis[d];
    float sc = dd * dd;
    float2 acc = ((const float2*)(g_t + (size_t)d * HID))[lane];
    acc.x *= sc; acc.y *= sc;

    int e0 = g_rowptr[d], e1 = g_rowptr[d + 1];
    for (int e = e0; e < e1; e++) {
        int s = g_csr_src[e];            // broadcast load
        float nrm = g_csr_norm[e];       // broadcast load
        float2 v = ((const float2*)(g_t + (size_t)s * HID))[lane];
        acc.x += nrm * v.x;
        acc.y += nrm * v.y;
    }

    float b0 = b[2 * lane], b1 = b[2 * lane + 1];
    float x0 = acc.x + b0, x1 = acc.y + b1;
    g_h[(size_t)d * HID + 2 * lane]     = (x0 > 0.f) ? x0 : NEG * x0;
    g_h[(size_t)d * HID + 2 * lane + 1] = (x1 > 0.f) ? x1 : NEG * x1;
}

// ---------------- output: g_h[NN,64]@[64,40] + b, log_softmax ---------------
__global__ void __launch_bounds__(256)
out_kernel(const float* __restrict__ W, const float* __restrict__ b,
           float* __restrict__ out) {
    __shared__ float Ws[HID * NCLS];
    __shared__ float bs[NCLS];
    int tid = threadIdx.x;
    for (int i = tid; i < HID * NCLS; i += 256) Ws[i] = W[i];
    if (tid < NCLS) bs[tid] = b[tid];
    __syncthreads();

    int warp = tid >> 5, lane = tid & 31;
    long long node = (long long)blockIdx.x * 8 + warp;
    if (node >= NN) return;

    float hv0 = g_h[node * HID + lane];
    float hv1 = g_h[node * HID + 32 + lane];

    float a0 = bs[lane];
    float a1 = (lane < 8) ? bs[32 + lane] : 0.f;
#pragma unroll 8
    for (int k = 0; k < HID; k++) {
        float hk = __shfl_sync(0xffffffffu, (k < 32) ? hv0 : hv1, k & 31);
        a0 += hk * Ws[k * NCLS + lane];
        if (lane < 8) a1 += hk * Ws[k * NCLS + 32 + lane];
    }

    float m = (lane < 8) ? fmaxf(a0, a1) : a0;
#pragma unroll
    for (int o = 16; o > 0; o >>= 1)
        m = fmaxf(m, __shfl_xor_sync(0xffffffffu, m, o));

    float s = expf(a0 - m) + ((lane < 8) ? expf(a1 - m) : 0.f);
#pragma unroll
    for (int o = 16; o > 0; o >>= 1)
        s += __shfl_xor_sync(0xffffffffu, s, o);

    float lse = m + logf(s);
    out[node * NCLS + lane] = a0 - lse;
    if (lane < 8) out[node * NCLS + 32 + lane] = a1 - lse;
}

// ---------------- launch (kernel launches ONLY) ------------------------------
extern "C" void kernel_launch(void* const* d_in, const int* in_sizes, int n_in,
                              void* d_out, int out_size) {
    const float* x       = (const float*)d_in[0];
    const void*  ei      = d_in[1];
    const float* ew      = (const float*)d_in[2];
    const float* W_first = (const float*)d_in[3];
    const float* b_first = (const float*)d_in[4];
    const float* Wc1     = (const float*)d_in[5];
    const float* bc1     = (const float*)d_in[6];
    const float* Wc2     = (const float*)d_in[7];
    const float* bc2     = (const float*)d_in[8];
    const float* W_out   = (const float*)d_in[9];
    const float* b_out   = (const float*)d_in[10];
    float* out = (float*)d_out;

    const int T = 256;
    detect_i64_kernel<<<1, 1>>>(ei);

    // norm + CSR build
    init_kernel<<<(NN + T - 1) / T, T>>>();
    deg_accum_kernel<<<(NE + T - 1) / T, T>>>(ei, ew);
    dis_kernel<<<(NN + T - 1) / T, T>>>();
    scan1_kernel<<<NPART, 256>>>();
    scan2_kernel<<<1, 1>>>();
    scan3_kernel<<<NPART, 256>>>();
    fill_kernel<<<(NE + T - 1) / T, T>>>(ei, ew);

    // first linear + leaky_relu -> g_h
    gemm128_bias_lrelu<<<NN / 16, T>>>(x, W_first, b_first);

    // conv layer 1
    gemm64<<<NN / 32, T>>>(Wc1);
    agg_kernel<<<(NN * 32 + T - 1) / T, T>>>(bc1);

    // conv layer 2
    gemm64<<<NN / 32, T>>>(Wc2);
    agg_kernel<<<(NN * 32 + T - 1) / T, T>>>(bc2);

    // output head + log_softmax
    out_kernel<<<(NN + 7) / 8, T>>>(W_out, b_out, out);
}